// round 5
// baseline (speedup 1.0000x reference)
#include <cuda_runtime.h>
#include <math_constants.h>
#include <cstdint>

#define DIM    1024
#define NHEAD  16
#define HDIM   64
#define BATCH  4
#define SEQ    2048
#define MTOT   (BATCH * SEQ)      // 8192

// ---------------------------------------------------------------------------
// Scratch
// ---------------------------------------------------------------------------
__device__ float g_QKV[3 * MTOT * DIM];   // Q(pre-scaled),K,V  (tf32-rounded)
__device__ float g_AO [MTOT * DIM];       // attention out (tf32-rounded)
__device__ float g_Xt [MTOT * DIM];       // tf32-rounded x
__device__ float g_Wt [4 * DIM * DIM];    // tf32-rounded Wq,Wk,Wv,Wo

// ---------------------------------------------------------------------------
// Helpers
// ---------------------------------------------------------------------------
__device__ __forceinline__ unsigned f2tf(float x) {
    unsigned u;
    asm("cvt.rna.tf32.f32 %0, %1;" : "=r"(u) : "f"(x));
    return u;
}

__device__ __forceinline__ uint32_t smem_u32(const void* p) {
    uint32_t a;
    asm("{ .reg .u64 t; cvta.to.shared.u64 t, %1; cvt.u32.u64 %0, t; }"
        : "=r"(a) : "l"(p));
    return a;
}

__device__ __forceinline__ void mma_tf32(float* c,
                                         unsigned a0, unsigned a1,
                                         unsigned a2, unsigned a3,
                                         unsigned b0, unsigned b1) {
    asm volatile(
        "mma.sync.aligned.m16n8k8.row.col.f32.tf32.tf32.f32 "
        "{%0,%1,%2,%3},{%4,%5,%6,%7},{%8,%9},{%0,%1,%2,%3};\n"
        : "+f"(c[0]), "+f"(c[1]), "+f"(c[2]), "+f"(c[3])
        : "r"(a0), "r"(a1), "r"(a2), "r"(a3), "r"(b0), "r"(b1));
}

#define LDSM_X4(r0, r1, r2, r3, addr)                                         \
    asm volatile("ldmatrix.sync.aligned.m8n8.x4.shared.b16 {%0,%1,%2,%3}, [%4];" \
                 : "=r"(r0), "=r"(r1), "=r"(r2), "=r"(r3) : "r"(addr))

#define CP_ASYNC16(dst, src) \
    asm volatile("cp.async.cg.shared.global [%0], [%1], 16;" \
                 :: "r"(dst), "l"(src) : "memory")
#define CP_COMMIT() asm volatile("cp.async.commit_group;" ::: "memory")
#define CP_WAIT(N)  asm volatile("cp.async.wait_group %0;" :: "n"(N) : "memory")

// ---------------------------------------------------------------------------
// Pre-pass: fp32 -> tf32-rounded fp32
// ---------------------------------------------------------------------------
__global__ void cvt_x_k(const float4* __restrict__ src,
                        float4* __restrict__ dst, int n4)
{
    int i = blockIdx.x * blockDim.x + threadIdx.x;
    int stride = gridDim.x * blockDim.x;
    for (; i < n4; i += stride) {
        float4 v = src[i];
        v.x = __uint_as_float(f2tf(v.x));
        v.y = __uint_as_float(f2tf(v.y));
        v.z = __uint_as_float(f2tf(v.z));
        v.w = __uint_as_float(f2tf(v.w));
        dst[i] = v;
    }
}

__global__ void cvt_w_k(const float4* __restrict__ w0, const float4* __restrict__ w1,
                        const float4* __restrict__ w2, const float4* __restrict__ w3,
                        float4* __restrict__ dst)
{
    const float4* src = (blockIdx.y == 0) ? w0 : (blockIdx.y == 1) ? w1
                       : (blockIdx.y == 2) ? w2 : w3;
    float4* d = dst + (size_t)blockIdx.y * (DIM * DIM / 4);
    const int n4 = DIM * DIM / 4;
    int i = blockIdx.x * blockDim.x + threadIdx.x;
    int stride = gridDim.x * blockDim.x;
    for (; i < n4; i += stride) {
        float4 v = src[i];
        v.x = __uint_as_float(f2tf(v.x));
        v.y = __uint_as_float(f2tf(v.y));
        v.z = __uint_as_float(f2tf(v.z));
        v.w = __uint_as_float(f2tf(v.w));
        d[i] = v;
    }
}

// ---------------------------------------------------------------------------
// TF32 GEMM: C = A * W^T. Tile 128(M) x 256(N), BK=32, 3-stage cp.async.
// 256 threads / 8 warps, warp tile 64x64, ldmatrix fragment loads.
// Smem rows stride 36 words (144B): LDSM conflict-free, 16B aligned.
// grid.z selects W / C slab. Q slab (z==0 when SCALEQ) scaled by 0.125.
// ---------------------------------------------------------------------------
#define BK      32
#define NCH     (DIM / BK)              // 32
#define GROWB   144                     // bytes per smem row (36 words)
#define A_STGB  (128 * GROWB)           // 18432
#define B_STGB  (256 * GROWB)           // 36864
#define STGB    (A_STGB + B_STGB)       // 55296
#define SMEM_GEMM (3 * STGB)            // 165888

template<bool ROUND, bool SCALEQ>
__global__ __launch_bounds__(256)
void gemm_tc(const float* __restrict__ Abase,
             const float* __restrict__ Wbase,
             float* __restrict__ Cbase)
{
    extern __shared__ float smf[];
    const uint32_t sbase = smem_u32(smf);

    const int tid  = threadIdx.x;
    const int lane = tid & 31;
    const int warp = tid >> 5;
    const int wm   = warp & 1;           // m offset wm*64
    const int wn   = warp >> 1;          // n offset wn*64
    const int r    = lane >> 2;
    const int t    = lane & 3;
    const int m0   = blockIdx.y * 128;
    const int n0   = blockIdx.x * 256;

    const float* A = Abase;
    const float* W = Wbase + (size_t)blockIdx.z * DIM * DIM;
    float*       C = Cbase + (size_t)blockIdx.z * MTOT * DIM;

    float c[4][8][4];
    #pragma unroll
    for (int mi = 0; mi < 4; ++mi)
        #pragma unroll
        for (int ni = 0; ni < 8; ++ni)
            #pragma unroll
            for (int j = 0; j < 4; ++j) c[mi][ni][j] = 0.0f;

    // LDSM per-lane base offsets
    const int arow  = ((lane >> 3) & 1) * 8 + (lane & 7);
    const int abyte = (lane >> 4) * 16;
    const int brow  = ((lane >> 4) & 1) * 8 + (lane & 7);
    const int bbyte = ((lane >> 3) & 1) * 16;
    const uint32_t aFrag = (uint32_t)((wm * 64 + arow) * GROWB + abyte);
    const uint32_t bFrag = (uint32_t)(A_STGB + (wn * 64 + brow) * GROWB + bbyte);

    auto load_stage = [&](int ch, int s) {
        const float* Ab = A + (size_t)m0 * DIM + ch * BK;
        const float* Wb = W + (size_t)n0 * DIM + ch * BK;
        const uint32_t as = sbase + s * STGB;
        const uint32_t bs = as + A_STGB;
        #pragma unroll
        for (int p = 0; p < 4; ++p) {             // A: 1024 uint4
            int slot = tid + p * 256;
            int row  = slot >> 3;
            int cb   = (slot & 7) * 16;
            CP_ASYNC16(as + row * GROWB + cb,
                       Ab + (size_t)row * DIM + (slot & 7) * 4);
        }
        #pragma unroll
        for (int p = 0; p < 8; ++p) {             // B: 2048 uint4
            int slot = tid + p * 256;
            int row  = slot >> 3;
            int cb   = (slot & 7) * 16;
            CP_ASYNC16(bs + row * GROWB + cb,
                       Wb + (size_t)row * DIM + (slot & 7) * 4);
        }
        CP_COMMIT();
    };

    load_stage(0, 0);
    load_stage(1, 1);

    for (int ch = 0; ch < NCH; ++ch) {
        if (ch < NCH - 1) { CP_WAIT(1); } else { CP_WAIT(0); }
        __syncthreads();
        if (ch + 2 < NCH) load_stage(ch + 2, (ch + 2) % 3);

        const uint32_t stg = sbase + (ch % 3) * STGB;
        const uint32_t aB  = stg + aFrag;
        const uint32_t bB  = stg + bFrag;

        #pragma unroll
        for (int ks = 0; ks < 4; ++ks) {
            unsigned a[4][4], b[4][4];
            #pragma unroll
            for (int mi = 0; mi < 4; ++mi)
                LDSM_X4(a[mi][0], a[mi][1], a[mi][2], a[mi][3],
                        aB + mi * (16 * GROWB) + ks * 32);
            #pragma unroll
            for (int pi = 0; pi < 4; ++pi)
                LDSM_X4(b[pi][0], b[pi][1], b[pi][2], b[pi][3],
                        bB + pi * (16 * GROWB) + ks * 32);
            #pragma unroll
            for (int mi = 0; mi < 4; ++mi)
                #pragma unroll
                for (int pi = 0; pi < 4; ++pi) {
                    mma_tf32(c[mi][2*pi],   a[mi][0], a[mi][1], a[mi][2], a[mi][3],
                             b[pi][0], b[pi][1]);
                    mma_tf32(c[mi][2*pi+1], a[mi][0], a[mi][1], a[mi][2], a[mi][3],
                             b[pi][2], b[pi][3]);
                }
        }
    }

    const float sc = (SCALEQ && blockIdx.z == 0) ? 0.125f : 1.0f;
    #pragma unroll
    for (int mi = 0; mi < 4; ++mi) {
        #pragma unroll
        for (int ni = 0; ni < 8; ++ni) {
            int row = m0 + wm * 64 + mi * 16 + r;
            int col = n0 + wn * 64 + ni * 8 + 2 * t;
            float v0 = c[mi][ni][0] * sc, v1 = c[mi][ni][1] * sc;
            float v2 = c[mi][ni][2] * sc, v3 = c[mi][ni][3] * sc;
            if (ROUND) {
                v0 = __uint_as_float(f2tf(v0)); v1 = __uint_as_float(f2tf(v1));
                v2 = __uint_as_float(f2tf(v2)); v3 = __uint_as_float(f2tf(v3));
            }
            *reinterpret_cast<float2*>(&C[(size_t)row * DIM + col])       = make_float2(v0, v1);
            *reinterpret_cast<float2*>(&C[(size_t)(row + 8) * DIM + col]) = make_float2(v2, v3);
        }
    }
}

// ---------------------------------------------------------------------------
// Flash attention, ldmatrix fragments. Q-tile 128 (8 warps), K-tile 64.
// Q pre-scaled by 0.125 at projection time. V stored transposed in smem.
// Heavy tiles launched first (reversed blockIdx.x).
// ---------------------------------------------------------------------------
#define FST 68                                 // smem row stride (words)
#define FSTB (FST * 4)                         // 272 bytes
#define FL_SMEMW ((128 + 64 + 128 + 64) * FST) // 26112 words = 104448 B

__global__ __launch_bounds__(256, 2)
void flash_tf32(const float* __restrict__ Q,
                const float* __restrict__ K,
                const float* __restrict__ V,
                float* __restrict__ O)
{
    extern __shared__ unsigned sm[];
    unsigned* Qs = sm;                    // [128][FST]  q rows x d
    unsigned* Ks = sm + 128 * FST;        // [64][FST]   k rows x d
    unsigned* Ps = sm + 192 * FST;        // [128][FST]  q rows x k
    unsigned* Vt = sm + 320 * FST;        // [64][FST]   d rows x k (transposed!)

    const int tid  = threadIdx.x;
    const int lane = tid & 31;
    const int warp = tid >> 5;            // 0..7
    const int r    = lane >> 2;
    const int t    = lane & 3;
    const int qt   = (gridDim.x - 1) - blockIdx.x;   // heavy first
    const int h    = blockIdx.y;
    const int b    = blockIdx.z;
    const int q0   = qt * 128;
    const size_t base = (size_t)b * SEQ * DIM + (size_t)h * HDIM;

    const uint32_t smb   = smem_u32(sm);
    const int arow  = ((lane >> 3) & 1) * 8 + (lane & 7);
    const int abyte = (lane >> 4) * 16;
    const int brow  = ((lane >> 4) & 1) * 8 + (lane & 7);
    const int bbyte = ((lane >> 3) & 1) * 16;
    const uint32_t qFrag = smb + (warp * 16 + arow) * FSTB + abyte;
    const uint32_t kFrag = smb + 128 * FSTB + brow * FSTB + bbyte;
    const uint32_t pFrag = smb + 192 * FSTB + (warp * 16 + arow) * FSTB + abyte;
    const uint32_t vFrag = smb + 320 * FSTB + brow * FSTB + bbyte;

    // Q tile: 128 rows x 16 uint4 (8/thread), raw bits (already tf32)
    #pragma unroll
    for (int p = 0; p < 8; ++p) {
        int slot = tid + p * 256;
        int row  = slot >> 4;
        int c4   = (slot & 15) * 4;
        uint4 v = *reinterpret_cast<const uint4*>(
            &Q[base + (size_t)(q0 + row) * DIM + c4]);
        *reinterpret_cast<uint4*>(&Qs[row * FST + c4]) = v;
    }

    float m_i[2] = {-CUDART_INF_F, -CUDART_INF_F};
    float l_i[2] = {0.0f, 0.0f};
    float o[8][4];
    #pragma unroll
    for (int ni = 0; ni < 8; ++ni)
        #pragma unroll
        for (int j = 0; j < 4; ++j) o[ni][j] = 0.0f;

    const int row_loc = warp * 16 + r;
    const int ktmax   = 2 * qt + 1;

    for (int kt = 0; kt <= ktmax; ++kt) {
        const int k0 = kt * 64;
        // K natural [k][d], V transposed -> Vt[d][k]
        #pragma unroll
        for (int p = 0; p < 4; ++p) {
            int slot = tid + p * 256;
            int row  = slot >> 4;
            int c4   = (slot & 15) * 4;
            uint4 kv = *reinterpret_cast<const uint4*>(
                &K[base + (size_t)(k0 + row) * DIM + c4]);
            *reinterpret_cast<uint4*>(&Ks[row * FST + c4]) = kv;
            uint4 vv = *reinterpret_cast<const uint4*>(
                &V[base + (size_t)(k0 + row) * DIM + c4]);
            Vt[(c4 + 0) * FST + row] = vv.x;
            Vt[(c4 + 1) * FST + row] = vv.y;
            Vt[(c4 + 2) * FST + row] = vv.z;
            Vt[(c4 + 3) * FST + row] = vv.w;
        }
        __syncthreads();

        const bool active = (k0 <= q0 + warp * 16 + 15);
        if (active) {
            // ---- S = Q K^T (Q pre-scaled) ----
            float s[8][4];
            #pragma unroll
            for (int ni = 0; ni < 8; ++ni)
                #pragma unroll
                for (int j = 0; j < 4; ++j) s[ni][j] = 0.0f;

            #pragma unroll
            for (int ks = 0; ks < 8; ++ks) {
                unsigned a0, a1, a2, a3;
                LDSM_X4(a0, a1, a2, a3, qFrag + ks * 32);
                #pragma unroll
                for (int pi = 0; pi < 4; ++pi) {
                    unsigned b0, b1, b2, b3;
                    LDSM_X4(b0, b1, b2, b3, kFrag + pi * (16 * FSTB) + ks * 32);
                    mma_tf32(s[2*pi],   a0, a1, a2, a3, b0, b1);
                    mma_tf32(s[2*pi+1], a0, a1, a2, a3, b2, b3);
                }
            }

            // ---- causal mask (diagonal tiles only) ----
            if (k0 + 63 > q0 + warp * 16) {
                const int rg0 = q0 + row_loc;
                #pragma unroll
                for (int ni = 0; ni < 8; ++ni) {
                    int cg = k0 + ni * 8 + 2 * t;
                    if (cg     > rg0    ) s[ni][0] = -CUDART_INF_F;
                    if (cg + 1 > rg0    ) s[ni][1] = -CUDART_INF_F;
                    if (cg     > rg0 + 8) s[ni][2] = -CUDART_INF_F;
                    if (cg + 1 > rg0 + 8) s[ni][3] = -CUDART_INF_F;
                }
            }

            // ---- online softmax (rows r, r+8), width-4 shuffles ----
            #pragma unroll
            for (int hh = 0; hh < 2; ++hh) {
                float mx = -CUDART_INF_F;
                #pragma unroll
                for (int ni = 0; ni < 8; ++ni)
                    mx = fmaxf(mx, fmaxf(s[ni][hh * 2], s[ni][hh * 2 + 1]));
                mx = fmaxf(mx, __shfl_xor_sync(0xffffffffu, mx, 1, 4));
                mx = fmaxf(mx, __shfl_xor_sync(0xffffffffu, mx, 2, 4));
                float mnew  = fmaxf(m_i[hh], mx);
                float alpha = __expf(m_i[hh] - mnew);
                m_i[hh] = mnew;
                float rs = 0.0f;
                #pragma unroll
                for (int ni = 0; ni < 8; ++ni) {
                    float p0 = __expf(s[ni][hh * 2]     - mnew);
                    float p1 = __expf(s[ni][hh * 2 + 1] - mnew);
                    s[ni][hh * 2]     = p0;
                    s[ni][hh * 2 + 1] = p1;
                    rs += p0 + p1;
                }
                rs += __shfl_xor_sync(0xffffffffu, rs, 1, 4);
                rs += __shfl_xor_sync(0xffffffffu, rs, 2, 4);
                l_i[hh] = l_i[hh] * alpha + rs;
                #pragma unroll
                for (int ni = 0; ni < 8; ++ni) {
                    o[ni][hh * 2]     *= alpha;
                    o[ni][hh * 2 + 1] *= alpha;
                }
            }

            // ---- stage P (tf32 bits, own rows) ----
            #pragma unroll
            for (int ni = 0; ni < 8; ++ni) {
                uint2 p01 = make_uint2(f2tf(s[ni][0]), f2tf(s[ni][1]));
                uint2 p23 = make_uint2(f2tf(s[ni][2]), f2tf(s[ni][3]));
                *reinterpret_cast<uint2*>(&Ps[row_loc * FST + ni * 8 + 2 * t])       = p01;
                *reinterpret_cast<uint2*>(&Ps[(row_loc + 8) * FST + ni * 8 + 2 * t]) = p23;
            }
            __syncwarp();

            // ---- O += P V ----
            #pragma unroll
            for (int ks = 0; ks < 8; ++ks) {
                unsigned a0, a1, a2, a3;
                LDSM_X4(a0, a1, a2, a3, pFrag + ks * 32);
                #pragma unroll
                for (int pi = 0; pi < 4; ++pi) {
                    unsigned b0, b1, b2, b3;
                    LDSM_X4(b0, b1, b2, b3, vFrag + pi * (16 * FSTB) + ks * 32);
                    mma_tf32(o[2*pi],   a0, a1, a2, a3, b0, b1);
                    mma_tf32(o[2*pi+1], a0, a1, a2, a3, b2, b3);
                }
            }
        }
        __syncthreads();
    }

    // ---- normalize + tf32-rounded store ----
    #pragma unroll
    for (int hh = 0; hh < 2; ++hh) {
        float inv_l = 1.0f / l_i[hh];
        int row = q0 + row_loc + hh * 8;
        #pragma unroll
        for (int ni = 0; ni < 8; ++ni) {
            float v0 = __uint_as_float(f2tf(o[ni][hh * 2]     * inv_l));
            float v1 = __uint_as_float(f2tf(o[ni][hh * 2 + 1] * inv_l));
            *reinterpret_cast<float2*>(
                &O[base + (size_t)row * DIM + ni * 8 + 2 * t]) = make_float2(v0, v1);
        }
    }
}

// ---------------------------------------------------------------------------
// Launch
// ---------------------------------------------------------------------------
extern "C" void kernel_launch(void* const* d_in, const int* in_sizes, int n_in,
                              void* d_out, int out_size)
{
    const float* x  = (const float*)d_in[0];
    const float* Wq = (const float*)d_in[2];
    const float* Wk = (const float*)d_in[3];
    const float* Wv = (const float*)d_in[4];
    const float* Wo = (const float*)d_in[5];
    float* out = (float*)d_out;

    float *QKV, *AOd, *Xt, *Wt;
    cudaGetSymbolAddress((void**)&QKV, g_QKV);
    cudaGetSymbolAddress((void**)&AOd, g_AO);
    cudaGetSymbolAddress((void**)&Xt,  g_Xt);
    cudaGetSymbolAddress((void**)&Wt,  g_Wt);

    const int smem_flash = FL_SMEMW * sizeof(unsigned);   // 104448
    static bool attr_set = false;
    if (!attr_set) {
        cudaFuncSetAttribute(flash_tf32,
                             cudaFuncAttributeMaxDynamicSharedMemorySize, smem_flash);
        cudaFuncSetAttribute((gemm_tc<true, true>),
                             cudaFuncAttributeMaxDynamicSharedMemorySize, SMEM_GEMM);
        cudaFuncSetAttribute((gemm_tc<false, false>),
                             cudaFuncAttributeMaxDynamicSharedMemorySize, SMEM_GEMM);
        attr_set = true;
    }

    cvt_x_k<<<1024, 256>>>((const float4*)x, (float4*)Xt, MTOT * DIM / 4);
    cvt_w_k<<<dim3(128, 4), 256>>>((const float4*)Wq, (const float4*)Wk,
                                   (const float4*)Wv, (const float4*)Wo, (float4*)Wt);

    // fused Q,K,V projections; Q pre-scaled by 0.125 (exact)
    dim3 gQKV(DIM / 256, MTOT / 128, 3);   // (4, 64, 3)
    gemm_tc<true, true><<<gQKV, 256, SMEM_GEMM>>>(Xt, Wt, QKV);

    const float* Qd = QKV;
    const float* Kd = QKV + (size_t)MTOT * DIM;
    const float* Vd = QKV + 2 * (size_t)MTOT * DIM;

    dim3 gF(SEQ / 128, NHEAD, BATCH);      // (16, 16, 4)
    flash_tf32<<<gF, 256, smem_flash>>>(Qd, Kd, Vd, AOd);

    dim3 gO(DIM / 256, MTOT / 128, 1);
    gemm_tc<false, false><<<gO, 256, SMEM_GEMM>>>(AOd, Wt + 3 * (size_t)DIM * DIM, out);
}

// round 6
// speedup vs baseline: 1.0358x; 1.0358x over previous
#include <cuda_runtime.h>
#include <math_constants.h>
#include <cstdint>

#define DIM    1024
#define NHEAD  16
#define HDIM   64
#define BATCH  4
#define SEQ    2048
#define MTOT   (BATCH * SEQ)      // 8192

// Q pre-scale: 64^-0.5 * log2(e)  (softmax done in base 2)
#define QSCALE 0.18033688011112042f

// ---------------------------------------------------------------------------
// Scratch
// ---------------------------------------------------------------------------
__device__ float g_QKV[3 * MTOT * DIM];   // Q(pre-scaled),K,V  (tf32-rounded)
__device__ float g_AO [MTOT * DIM];       // attention out (tf32-rounded)
__device__ float g_Xt [MTOT * DIM];       // tf32-rounded x
__device__ float g_Wt [4 * DIM * DIM];    // tf32-rounded Wq,Wk,Wv,Wo

// ---------------------------------------------------------------------------
// Helpers
// ---------------------------------------------------------------------------
__device__ __forceinline__ unsigned f2tf(float x) {
    unsigned u;
    asm("cvt.rna.tf32.f32 %0, %1;" : "=r"(u) : "f"(x));
    return u;
}

__device__ __forceinline__ float ex2f(float x) {
    float y;
    asm("ex2.approx.f32 %0, %1;" : "=f"(y) : "f"(x));
    return y;
}

__device__ __forceinline__ uint32_t smem_u32(const void* p) {
    uint32_t a;
    asm("{ .reg .u64 t; cvta.to.shared.u64 t, %1; cvt.u32.u64 %0, t; }"
        : "=r"(a) : "l"(p));
    return a;
}

__device__ __forceinline__ void mma_tf32(float* c,
                                         unsigned a0, unsigned a1,
                                         unsigned a2, unsigned a3,
                                         unsigned b0, unsigned b1) {
    asm volatile(
        "mma.sync.aligned.m16n8k8.row.col.f32.tf32.tf32.f32 "
        "{%0,%1,%2,%3},{%4,%5,%6,%7},{%8,%9},{%0,%1,%2,%3};\n"
        : "+f"(c[0]), "+f"(c[1]), "+f"(c[2]), "+f"(c[3])
        : "r"(a0), "r"(a1), "r"(a2), "r"(a3), "r"(b0), "r"(b1));
}

#define LDSM_X4(r0, r1, r2, r3, addr)                                         \
    asm volatile("ldmatrix.sync.aligned.m8n8.x4.shared.b16 {%0,%1,%2,%3}, [%4];" \
                 : "=r"(r0), "=r"(r1), "=r"(r2), "=r"(r3) : "r"(addr))

#define CP_ASYNC16(dst, src) \
    asm volatile("cp.async.cg.shared.global [%0], [%1], 16;" \
                 :: "r"(dst), "l"(src) : "memory")
#define CP_COMMIT() asm volatile("cp.async.commit_group;" ::: "memory")
#define CP_WAIT(N)  asm volatile("cp.async.wait_group %0;" :: "n"(N) : "memory")

// ---------------------------------------------------------------------------
// Pre-pass: fp32 -> tf32-rounded fp32
// ---------------------------------------------------------------------------
__global__ void cvt_x_k(const float4* __restrict__ src,
                        float4* __restrict__ dst, int n4)
{
    int i = blockIdx.x * blockDim.x + threadIdx.x;
    int stride = gridDim.x * blockDim.x;
    for (; i < n4; i += stride) {
        float4 v = src[i];
        v.x = __uint_as_float(f2tf(v.x));
        v.y = __uint_as_float(f2tf(v.y));
        v.z = __uint_as_float(f2tf(v.z));
        v.w = __uint_as_float(f2tf(v.w));
        dst[i] = v;
    }
}

__global__ void cvt_w_k(const float4* __restrict__ w0, const float4* __restrict__ w1,
                        const float4* __restrict__ w2, const float4* __restrict__ w3,
                        float4* __restrict__ dst)
{
    const float4* src = (blockIdx.y == 0) ? w0 : (blockIdx.y == 1) ? w1
                       : (blockIdx.y == 2) ? w2 : w3;
    float4* d = dst + (size_t)blockIdx.y * (DIM * DIM / 4);
    const int n4 = DIM * DIM / 4;
    int i = blockIdx.x * blockDim.x + threadIdx.x;
    int stride = gridDim.x * blockDim.x;
    for (; i < n4; i += stride) {
        float4 v = src[i];
        v.x = __uint_as_float(f2tf(v.x));
        v.y = __uint_as_float(f2tf(v.y));
        v.z = __uint_as_float(f2tf(v.z));
        v.w = __uint_as_float(f2tf(v.w));
        d[i] = v;
    }
}

// ---------------------------------------------------------------------------
// TF32 GEMM: C = A * W^T. Tile 128(M) x 256(N), BK=32, 3-stage cp.async.
// 512 threads / 16 warps, warp tile 32x64 (64 accum regs -> high occupancy).
// Smem rows stride 36 words (144B): LDSM conflict-free, 16B aligned.
// grid.z selects W / C slab. Q slab (z==0 when SCALEQ) scaled by QSCALE.
// ---------------------------------------------------------------------------
#define BK      32
#define NCH     (DIM / BK)              // 32
#define GROWB   144                     // bytes per smem row (36 words)
#define A_STGB  (128 * GROWB)           // 18432
#define B_STGB  (256 * GROWB)           // 36864
#define STGB    (A_STGB + B_STGB)       // 55296
#define SMEM_GEMM (3 * STGB)            // 165888

template<bool ROUND, bool SCALEQ>
__global__ __launch_bounds__(512, 1)
void gemm_tc(const float* __restrict__ Abase,
             const float* __restrict__ Wbase,
             float* __restrict__ Cbase)
{
    extern __shared__ float smf[];
    const uint32_t sbase = smem_u32(smf);

    const int tid  = threadIdx.x;
    const int lane = tid & 31;
    const int warp = tid >> 5;           // 0..15
    const int wm   = warp & 3;           // m offset wm*32
    const int wn   = warp >> 2;          // n offset wn*64
    const int r    = lane >> 2;
    const int t    = lane & 3;
    const int m0   = blockIdx.y * 128;
    const int n0   = blockIdx.x * 256;

    const float* A = Abase;
    const float* W = Wbase + (size_t)blockIdx.z * DIM * DIM;
    float*       C = Cbase + (size_t)blockIdx.z * MTOT * DIM;

    float c[2][8][4];
    #pragma unroll
    for (int mi = 0; mi < 2; ++mi)
        #pragma unroll
        for (int ni = 0; ni < 8; ++ni)
            #pragma unroll
            for (int j = 0; j < 4; ++j) c[mi][ni][j] = 0.0f;

    // LDSM per-lane base offsets
    const int arow  = ((lane >> 3) & 1) * 8 + (lane & 7);
    const int abyte = (lane >> 4) * 16;
    const int brow  = ((lane >> 4) & 1) * 8 + (lane & 7);
    const int bbyte = ((lane >> 3) & 1) * 16;
    const uint32_t aFrag = (uint32_t)((wm * 32 + arow) * GROWB + abyte);
    const uint32_t bFrag = (uint32_t)(A_STGB + (wn * 64 + brow) * GROWB + bbyte);

    auto load_stage = [&](int ch, int s) {
        const float* Ab = A + (size_t)m0 * DIM + ch * BK;
        const float* Wb = W + (size_t)n0 * DIM + ch * BK;
        const uint32_t as = sbase + s * STGB;
        const uint32_t bs = as + A_STGB;
        #pragma unroll
        for (int p = 0; p < 2; ++p) {             // A: 1024 uint4
            int slot = tid + p * 512;
            int row  = slot >> 3;
            int cb   = (slot & 7) * 16;
            CP_ASYNC16(as + row * GROWB + cb,
                       Ab + (size_t)row * DIM + (slot & 7) * 4);
        }
        #pragma unroll
        for (int p = 0; p < 4; ++p) {             // B: 2048 uint4
            int slot = tid + p * 512;
            int row  = slot >> 3;
            int cb   = (slot & 7) * 16;
            CP_ASYNC16(bs + row * GROWB + cb,
                       Wb + (size_t)row * DIM + (slot & 7) * 4);
        }
        CP_COMMIT();
    };

    load_stage(0, 0);
    load_stage(1, 1);

    for (int ch = 0; ch < NCH; ++ch) {
        if (ch < NCH - 1) { CP_WAIT(1); } else { CP_WAIT(0); }
        __syncthreads();
        if (ch + 2 < NCH) load_stage(ch + 2, (ch + 2) % 3);

        const uint32_t stg = sbase + (ch % 3) * STGB;
        const uint32_t aB  = stg + aFrag;
        const uint32_t bB  = stg + bFrag;

        #pragma unroll
        for (int ks = 0; ks < 4; ++ks) {
            unsigned a[2][4], b[4][4];
            #pragma unroll
            for (int mi = 0; mi < 2; ++mi)
                LDSM_X4(a[mi][0], a[mi][1], a[mi][2], a[mi][3],
                        aB + mi * (16 * GROWB) + ks * 32);
            #pragma unroll
            for (int pi = 0; pi < 4; ++pi)
                LDSM_X4(b[pi][0], b[pi][1], b[pi][2], b[pi][3],
                        bB + pi * (16 * GROWB) + ks * 32);
            #pragma unroll
            for (int mi = 0; mi < 2; ++mi)
                #pragma unroll
                for (int pi = 0; pi < 4; ++pi) {
                    mma_tf32(c[mi][2*pi],   a[mi][0], a[mi][1], a[mi][2], a[mi][3],
                             b[pi][0], b[pi][1]);
                    mma_tf32(c[mi][2*pi+1], a[mi][0], a[mi][1], a[mi][2], a[mi][3],
                             b[pi][2], b[pi][3]);
                }
        }
    }

    const float sc = (SCALEQ && blockIdx.z == 0) ? QSCALE : 1.0f;
    #pragma unroll
    for (int mi = 0; mi < 2; ++mi) {
        #pragma unroll
        for (int ni = 0; ni < 8; ++ni) {
            int row = m0 + wm * 32 + mi * 16 + r;
            int col = n0 + wn * 64 + ni * 8 + 2 * t;
            float v0 = c[mi][ni][0] * sc, v1 = c[mi][ni][1] * sc;
            float v2 = c[mi][ni][2] * sc, v3 = c[mi][ni][3] * sc;
            if (ROUND) {
                v0 = __uint_as_float(f2tf(v0)); v1 = __uint_as_float(f2tf(v1));
                v2 = __uint_as_float(f2tf(v2)); v3 = __uint_as_float(f2tf(v3));
            }
            *reinterpret_cast<float2*>(&C[(size_t)row * DIM + col])       = make_float2(v0, v1);
            *reinterpret_cast<float2*>(&C[(size_t)(row + 8) * DIM + col]) = make_float2(v2, v3);
        }
    }
}

// ---------------------------------------------------------------------------
// Flash attention. Q-tile 128 (8 warps), K-tile 64.
// LDSM fragments for Q/K/P; V natural [k][d] with conflict-free scalar loads.
// Q pre-scaled by QSCALE -> base-2 online softmax (pure EX2).
// Heavy tiles launched first (reversed blockIdx.x).
// ---------------------------------------------------------------------------
#define FST 68                                 // Q/K/P smem row stride (words)
#define FSTB (FST * 4)                         // 272 bytes
#define VST 72                                 // V smem row stride (words)
#define FL_SMEMW ((128 + 64 + 128) * FST + 64 * VST)   // 26368 words

__global__ __launch_bounds__(256, 2)
void flash_tf32(const float* __restrict__ Q,
                const float* __restrict__ K,
                const float* __restrict__ V,
                float* __restrict__ O)
{
    extern __shared__ unsigned sm[];
    unsigned* Qs = sm;                    // [128][FST]  q rows x d
    unsigned* Ks = sm + 128 * FST;        // [64][FST]   k rows x d
    unsigned* Ps = sm + 192 * FST;        // [128][FST]  q rows x k
    unsigned* Vs = sm + 320 * FST;        // [64][VST]   k rows x d (natural)

    const int tid  = threadIdx.x;
    const int lane = tid & 31;
    const int warp = tid >> 5;            // 0..7
    const int r    = lane >> 2;
    const int t    = lane & 3;
    const int qt   = (gridDim.x - 1) - blockIdx.x;   // heavy first
    const int h    = blockIdx.y;
    const int b    = blockIdx.z;
    const int q0   = qt * 128;
    const size_t base = (size_t)b * SEQ * DIM + (size_t)h * HDIM;

    const uint32_t smb   = smem_u32(sm);
    const int arow  = ((lane >> 3) & 1) * 8 + (lane & 7);
    const int abyte = (lane >> 4) * 16;
    const int brow  = ((lane >> 4) & 1) * 8 + (lane & 7);
    const int bbyte = ((lane >> 3) & 1) * 16;
    const uint32_t qFrag = smb + (warp * 16 + arow) * FSTB + abyte;
    const uint32_t kFrag = smb + 128 * FSTB + brow * FSTB + bbyte;
    const uint32_t pFrag = smb + 192 * FSTB + (warp * 16 + arow) * FSTB + abyte;

    // Q tile: 128 rows x 16 uint4 (8/thread), raw bits (already tf32+scaled)
    #pragma unroll
    for (int p = 0; p < 8; ++p) {
        int slot = tid + p * 256;
        int row  = slot >> 4;
        int c4   = (slot & 15) * 4;
        uint4 v = *reinterpret_cast<const uint4*>(
            &Q[base + (size_t)(q0 + row) * DIM + c4]);
        *reinterpret_cast<uint4*>(&Qs[row * FST + c4]) = v;
    }

    float m_i[2] = {-CUDART_INF_F, -CUDART_INF_F};
    float l_i[2] = {0.0f, 0.0f};
    float o[8][4];
    #pragma unroll
    for (int ni = 0; ni < 8; ++ni)
        #pragma unroll
        for (int j = 0; j < 4; ++j) o[ni][j] = 0.0f;

    const int row_loc = warp * 16 + r;
    const int ktmax   = 2 * qt + 1;

    for (int kt = 0; kt <= ktmax; ++kt) {
        const int k0 = kt * 64;
        // K and V tiles: natural [k][d], uint4 stores (conflict-free)
        #pragma unroll
        for (int p = 0; p < 4; ++p) {
            int slot = tid + p * 256;
            int row  = slot >> 4;
            int c4   = (slot & 15) * 4;
            uint4 kv = *reinterpret_cast<const uint4*>(
                &K[base + (size_t)(k0 + row) * DIM + c4]);
            *reinterpret_cast<uint4*>(&Ks[row * FST + c4]) = kv;
            uint4 vv = *reinterpret_cast<const uint4*>(
                &V[base + (size_t)(k0 + row) * DIM + c4]);
            *reinterpret_cast<uint4*>(&Vs[row * VST + c4]) = vv;
        }
        __syncthreads();

        const bool active = (k0 <= q0 + warp * 16 + 15);
        if (active) {
            // ---- S = Q K^T (Q pre-scaled, base-2 logits) ----
            float s[8][4];
            #pragma unroll
            for (int ni = 0; ni < 8; ++ni)
                #pragma unroll
                for (int j = 0; j < 4; ++j) s[ni][j] = 0.0f;

            #pragma unroll
            for (int ks = 0; ks < 8; ++ks) {
                unsigned a0, a1, a2, a3;
                LDSM_X4(a0, a1, a2, a3, qFrag + ks * 32);
                #pragma unroll
                for (int pi = 0; pi < 4; ++pi) {
                    unsigned b0, b1, b2, b3;
                    LDSM_X4(b0, b1, b2, b3, kFrag + pi * (16 * FSTB) + ks * 32);
                    mma_tf32(s[2*pi],   a0, a1, a2, a3, b0, b1);
                    mma_tf32(s[2*pi+1], a0, a1, a2, a3, b2, b3);
                }
            }

            // ---- causal mask (diagonal tiles only) ----
            if (k0 + 63 > q0 + warp * 16) {
                const int rg0 = q0 + row_loc;
                #pragma unroll
                for (int ni = 0; ni < 8; ++ni) {
                    int cg = k0 + ni * 8 + 2 * t;
                    if (cg     > rg0    ) s[ni][0] = -CUDART_INF_F;
                    if (cg + 1 > rg0    ) s[ni][1] = -CUDART_INF_F;
                    if (cg     > rg0 + 8) s[ni][2] = -CUDART_INF_F;
                    if (cg + 1 > rg0 + 8) s[ni][3] = -CUDART_INF_F;
                }
            }

            // ---- base-2 online softmax (rows r, r+8), width-4 shuffles ----
            #pragma unroll
            for (int hh = 0; hh < 2; ++hh) {
                float mx = -CUDART_INF_F;
                #pragma unroll
                for (int ni = 0; ni < 8; ++ni)
                    mx = fmaxf(mx, fmaxf(s[ni][hh * 2], s[ni][hh * 2 + 1]));
                mx = fmaxf(mx, __shfl_xor_sync(0xffffffffu, mx, 1, 4));
                mx = fmaxf(mx, __shfl_xor_sync(0xffffffffu, mx, 2, 4));
                float mnew  = fmaxf(m_i[hh], mx);
                float alpha = ex2f(m_i[hh] - mnew);
                m_i[hh] = mnew;
                float rs = 0.0f;
                #pragma unroll
                for (int ni = 0; ni < 8; ++ni) {
                    float p0 = ex2f(s[ni][hh * 2]     - mnew);
                    float p1 = ex2f(s[ni][hh * 2 + 1] - mnew);
                    s[ni][hh * 2]     = p0;
                    s[ni][hh * 2 + 1] = p1;
                    rs += p0 + p1;
                }
                rs += __shfl_xor_sync(0xffffffffu, rs, 1, 4);
                rs += __shfl_xor_sync(0xffffffffu, rs, 2, 4);
                l_i[hh] = l_i[hh] * alpha + rs;
                #pragma unroll
                for (int ni = 0; ni < 8; ++ni) {
                    o[ni][hh * 2]     *= alpha;
                    o[ni][hh * 2 + 1] *= alpha;
                }
            }

            // ---- stage P (tf32 bits, own rows; conflict-free 64b stores) ----
            #pragma unroll
            for (int ni = 0; ni < 8; ++ni) {
                uint2 p01 = make_uint2(f2tf(s[ni][0]), f2tf(s[ni][1]));
                uint2 p23 = make_uint2(f2tf(s[ni][2]), f2tf(s[ni][3]));
                *reinterpret_cast<uint2*>(&Ps[row_loc * FST + ni * 8 + 2 * t])       = p01;
                *reinterpret_cast<uint2*>(&Ps[(row_loc + 8) * FST + ni * 8 + 2 * t]) = p23;
            }
            __syncwarp();

            // ---- O += P V : LDSM A-frags, scalar V B-frags (conflict-free) ----
            #pragma unroll
            for (int ks = 0; ks < 8; ++ks) {
                unsigned a0, a1, a2, a3;
                LDSM_X4(a0, a1, a2, a3, pFrag + ks * 32);
                #pragma unroll
                for (int ni = 0; ni < 8; ++ni) {
                    unsigned b0 = Vs[(ks * 8 + t) * VST + ni * 8 + r];
                    unsigned b1 = Vs[(ks * 8 + t + 4) * VST + ni * 8 + r];
                    mma_tf32(o[ni], a0, a1, a2, a3, b0, b1);
                }
            }
        }
        __syncthreads();
    }

    // ---- normalize + tf32-rounded store ----
    #pragma unroll
    for (int hh = 0; hh < 2; ++hh) {
        float inv_l = 1.0f / l_i[hh];
        int row = q0 + row_loc + hh * 8;
        #pragma unroll
        for (int ni = 0; ni < 8; ++ni) {
            float v0 = __uint_as_float(f2tf(o[ni][hh * 2]     * inv_l));
            float v1 = __uint_as_float(f2tf(o[ni][hh * 2 + 1] * inv_l));
            *reinterpret_cast<float2*>(
                &O[base + (size_t)row * DIM + ni * 8 + 2 * t]) = make_float2(v0, v1);
        }
    }
}

// ---------------------------------------------------------------------------
// Launch
// ---------------------------------------------------------------------------
extern "C" void kernel_launch(void* const* d_in, const int* in_sizes, int n_in,
                              void* d_out, int out_size)
{
    const float* x  = (const float*)d_in[0];
    const float* Wq = (const float*)d_in[2];
    const float* Wk = (const float*)d_in[3];
    const float* Wv = (const float*)d_in[4];
    const float* Wo = (const float*)d_in[5];
    float* out = (float*)d_out;

    float *QKV, *AOd, *Xt, *Wt;
    cudaGetSymbolAddress((void**)&QKV, g_QKV);
    cudaGetSymbolAddress((void**)&AOd, g_AO);
    cudaGetSymbolAddress((void**)&Xt,  g_Xt);
    cudaGetSymbolAddress((void**)&Wt,  g_Wt);

    const int smem_flash = FL_SMEMW * sizeof(unsigned);   // 105472
    static bool attr_set = false;
    if (!attr_set) {
        cudaFuncSetAttribute(flash_tf32,
                             cudaFuncAttributeMaxDynamicSharedMemorySize, smem_flash);
        cudaFuncSetAttribute((gemm_tc<true, true>),
                             cudaFuncAttributeMaxDynamicSharedMemorySize, SMEM_GEMM);
        cudaFuncSetAttribute((gemm_tc<false, false>),
                             cudaFuncAttributeMaxDynamicSharedMemorySize, SMEM_GEMM);
        attr_set = true;
    }

    cvt_x_k<<<1024, 256>>>((const float4*)x, (float4*)Xt, MTOT * DIM / 4);
    cvt_w_k<<<dim3(128, 4), 256>>>((const float4*)Wq, (const float4*)Wk,
                                   (const float4*)Wv, (const float4*)Wo, (float4*)Wt);

    // fused Q,K,V projections; Q pre-scaled by 0.125*log2(e)
    dim3 gQKV(DIM / 256, MTOT / 128, 3);   // (4, 64, 3)
    gemm_tc<true, true><<<gQKV, 512, SMEM_GEMM>>>(Xt, Wt, QKV);

    const float* Qd = QKV;
    const float* Kd = QKV + (size_t)MTOT * DIM;
    const float* Vd = QKV + 2 * (size_t)MTOT * DIM;

    dim3 gF(SEQ / 128, NHEAD, BATCH);      // (16, 16, 4)
    flash_tf32<<<gF, 256, smem_flash>>>(Qd, Kd, Vd, AOd);

    dim3 gO(DIM / 256, MTOT / 128, 1);
    gemm_tc<false, false><<<gO, 512, SMEM_GEMM>>>(AOd, Wt + 3 * (size_t)DIM * DIM, out);
}

// round 7
// speedup vs baseline: 2.0173x; 1.9476x over previous
#include <cuda_runtime.h>
#include <cuda_fp16.h>
#include <math_constants.h>
#include <cstdint>

#define DIM    1024
#define NHEAD  16
#define HDIM   64
#define BATCH  4
#define SEQ    2048
#define MTOT   (BATCH * SEQ)      // 8192

// Q pre-scale: 64^-0.5 * log2(e)  (softmax done in base 2)
#define QSCALE 0.18033688011112042f

// ---------------------------------------------------------------------------
// Scratch (fp16 activations/weights)
// ---------------------------------------------------------------------------
__device__ __half g_QKV[3 * MTOT * DIM];   // Q(pre-scaled),K,V
__device__ __half g_AO [MTOT * DIM];       // attention out
__device__ __half g_Xh [MTOT * DIM];       // fp16 x
__device__ __half g_Wh [4 * DIM * DIM];    // fp16 Wq,Wk,Wv,Wo

// ---------------------------------------------------------------------------
// Helpers
// ---------------------------------------------------------------------------
__device__ __forceinline__ float ex2f(float x) {
    float y;
    asm("ex2.approx.f32 %0, %1;" : "=f"(y) : "f"(x));
    return y;
}

__device__ __forceinline__ uint32_t smem_u32(const void* p) {
    uint32_t a;
    asm("{ .reg .u64 t; cvta.to.shared.u64 t, %1; cvt.u32.u64 %0, t; }"
        : "=r"(a) : "l"(p));
    return a;
}

__device__ __forceinline__ void mma_f16(float* c,
                                        unsigned a0, unsigned a1,
                                        unsigned a2, unsigned a3,
                                        unsigned b0, unsigned b1) {
    asm volatile(
        "mma.sync.aligned.m16n8k16.row.col.f32.f16.f16.f32 "
        "{%0,%1,%2,%3},{%4,%5,%6,%7},{%8,%9},{%0,%1,%2,%3};\n"
        : "+f"(c[0]), "+f"(c[1]), "+f"(c[2]), "+f"(c[3])
        : "r"(a0), "r"(a1), "r"(a2), "r"(a3), "r"(b0), "r"(b1));
}

#define LDSM_X4(r0, r1, r2, r3, addr)                                         \
    asm volatile("ldmatrix.sync.aligned.m8n8.x4.shared.b16 {%0,%1,%2,%3}, [%4];" \
                 : "=r"(r0), "=r"(r1), "=r"(r2), "=r"(r3) : "r"(addr))

#define LDSM_X4T(r0, r1, r2, r3, addr)                                        \
    asm volatile("ldmatrix.sync.aligned.m8n8.x4.trans.shared.b16 {%0,%1,%2,%3}, [%4];" \
                 : "=r"(r0), "=r"(r1), "=r"(r2), "=r"(r3) : "r"(addr))

#define CP_ASYNC16(dst, src) \
    asm volatile("cp.async.cg.shared.global [%0], [%1], 16;" \
                 :: "r"(dst), "l"(src) : "memory")
#define CP_COMMIT() asm volatile("cp.async.commit_group;" ::: "memory")
#define CP_WAIT(N)  asm volatile("cp.async.wait_group %0;" :: "n"(N) : "memory")

// ---------------------------------------------------------------------------
// Pre-pass: fp32 -> fp16
// ---------------------------------------------------------------------------
__global__ void cvt_x_k(const float4* __restrict__ src,
                        __half2* __restrict__ dst, int n4)
{
    int i = blockIdx.x * blockDim.x + threadIdx.x;
    int stride = gridDim.x * blockDim.x;
    for (; i < n4; i += stride) {
        float4 v = src[i];
        dst[2 * i]     = __floats2half2_rn(v.x, v.y);
        dst[2 * i + 1] = __floats2half2_rn(v.z, v.w);
    }
}

__global__ void cvt_w_k(const float4* __restrict__ w0, const float4* __restrict__ w1,
                        const float4* __restrict__ w2, const float4* __restrict__ w3,
                        __half2* __restrict__ dst)
{
    const float4* src = (blockIdx.y == 0) ? w0 : (blockIdx.y == 1) ? w1
                       : (blockIdx.y == 2) ? w2 : w3;
    __half2* d = dst + (size_t)blockIdx.y * (DIM * DIM / 2);
    const int n4 = DIM * DIM / 4;
    int i = blockIdx.x * blockDim.x + threadIdx.x;
    int stride = gridDim.x * blockDim.x;
    for (; i < n4; i += stride) {
        float4 v = src[i];
        d[2 * i]     = __floats2half2_rn(v.x, v.y);
        d[2 * i + 1] = __floats2half2_rn(v.z, v.w);
    }
}

// ---------------------------------------------------------------------------
// FP16 GEMM: C = A * W^T. Tile 128(M) x 256(N), BK=64, 3-stage cp.async.
// 512 threads / 16 warps, warp tile 32x64, m16n8k16 mma, ldmatrix frags.
// Smem rows: 64 halves (128B) + 16B pad = 144B -> LDSM conflict-free.
// grid.z selects W / C slab. HALF_OUT: write __half C; else float.
// ---------------------------------------------------------------------------
#define BK      64
#define NCH     (DIM / BK)              // 16
#define GROWB   144
#define A_STGB  (128 * GROWB)           // 18432
#define B_STGB  (256 * GROWB)           // 36864
#define STGB    (A_STGB + B_STGB)       // 55296
#define SMEM_GEMM (3 * STGB)            // 165888

template<bool HALF_OUT, bool SCALEQ>
__global__ __launch_bounds__(512, 1)
void gemm_f16(const __half* __restrict__ Abase,
              const __half* __restrict__ Wbase,
              void* __restrict__ Cvoid)
{
    extern __shared__ char smc[];
    const uint32_t sbase = smem_u32(smc);

    const int tid  = threadIdx.x;
    const int lane = tid & 31;
    const int warp = tid >> 5;           // 0..15
    const int wm   = warp & 3;           // m offset wm*32
    const int wn   = warp >> 2;          // n offset wn*64
    const int r    = lane >> 2;
    const int t    = lane & 3;
    const int m0   = blockIdx.y * 128;
    const int n0   = blockIdx.x * 256;

    const __half* A = Abase;
    const __half* W = Wbase + (size_t)blockIdx.z * DIM * DIM;

    float c[2][8][4];
    #pragma unroll
    for (int mi = 0; mi < 2; ++mi)
        #pragma unroll
        for (int ni = 0; ni < 8; ++ni)
            #pragma unroll
            for (int j = 0; j < 4; ++j) c[mi][ni][j] = 0.0f;

    // LDSM per-lane addressing (byte offsets)
    const int arow  = ((lane >> 3) & 1) * 8 + (lane & 7);
    const int abyte = (lane >> 4) * 16;
    const int brow  = ((lane >> 4) & 1) * 8 + (lane & 7);
    const int bbyte = ((lane >> 3) & 1) * 16;
    const uint32_t aFrag = (uint32_t)((wm * 32 + arow) * GROWB + abyte);
    const uint32_t bFrag = (uint32_t)(A_STGB + (wn * 64 + brow) * GROWB + bbyte);

    auto load_stage = [&](int ch, int s) {
        const __half* Ab = A + (size_t)m0 * DIM + ch * BK;
        const __half* Wb = W + (size_t)n0 * DIM + ch * BK;
        const uint32_t as = sbase + s * STGB;
        const uint32_t bs = as + A_STGB;
        #pragma unroll
        for (int p = 0; p < 2; ++p) {             // A: 1024 x 16B
            int slot = tid + p * 512;
            int row  = slot >> 3;
            int c8   = (slot & 7) * 8;
            CP_ASYNC16(as + row * GROWB + c8 * 2,
                       Ab + (size_t)row * DIM + c8);
        }
        #pragma unroll
        for (int p = 0; p < 4; ++p) {             // B: 2048 x 16B
            int slot = tid + p * 512;
            int row  = slot >> 3;
            int c8   = (slot & 7) * 8;
            CP_ASYNC16(bs + row * GROWB + c8 * 2,
                       Wb + (size_t)row * DIM + c8);
        }
        CP_COMMIT();
    };

    load_stage(0, 0);
    load_stage(1, 1);

    for (int ch = 0; ch < NCH; ++ch) {
        if (ch < NCH - 1) { CP_WAIT(1); } else { CP_WAIT(0); }
        __syncthreads();
        if (ch + 2 < NCH) load_stage(ch + 2, (ch + 2) % 3);

        const uint32_t stg = sbase + (ch % 3) * STGB;
        const uint32_t aB  = stg + aFrag;
        const uint32_t bB  = stg + bFrag;

        #pragma unroll
        for (int ks = 0; ks < 4; ++ks) {          // k = 4 x 16
            unsigned a[2][4], b[4][4];
            #pragma unroll
            for (int mi = 0; mi < 2; ++mi)
                LDSM_X4(a[mi][0], a[mi][1], a[mi][2], a[mi][3],
                        aB + mi * (16 * GROWB) + ks * 32);
            #pragma unroll
            for (int pi = 0; pi < 4; ++pi)
                LDSM_X4(b[pi][0], b[pi][1], b[pi][2], b[pi][3],
                        bB + pi * (16 * GROWB) + ks * 32);
            #pragma unroll
            for (int mi = 0; mi < 2; ++mi)
                #pragma unroll
                for (int pi = 0; pi < 4; ++pi) {
                    mma_f16(c[mi][2*pi],   a[mi][0], a[mi][1], a[mi][2], a[mi][3],
                            b[pi][0], b[pi][1]);
                    mma_f16(c[mi][2*pi+1], a[mi][0], a[mi][1], a[mi][2], a[mi][3],
                            b[pi][2], b[pi][3]);
                }
        }
    }

    const float sc = (SCALEQ && blockIdx.z == 0) ? QSCALE : 1.0f;
    #pragma unroll
    for (int mi = 0; mi < 2; ++mi) {
        #pragma unroll
        for (int ni = 0; ni < 8; ++ni) {
            int row = m0 + wm * 32 + mi * 16 + r;
            int col = n0 + wn * 64 + ni * 8 + 2 * t;
            float v0 = c[mi][ni][0] * sc, v1 = c[mi][ni][1] * sc;
            float v2 = c[mi][ni][2] * sc, v3 = c[mi][ni][3] * sc;
            if (HALF_OUT) {
                __half* C = (__half*)Cvoid + (size_t)blockIdx.z * MTOT * DIM;
                *reinterpret_cast<__half2*>(&C[(size_t)row * DIM + col]) =
                    __floats2half2_rn(v0, v1);
                *reinterpret_cast<__half2*>(&C[(size_t)(row + 8) * DIM + col]) =
                    __floats2half2_rn(v2, v3);
            } else {
                float* C = (float*)Cvoid;
                *reinterpret_cast<float2*>(&C[(size_t)row * DIM + col])       = make_float2(v0, v1);
                *reinterpret_cast<float2*>(&C[(size_t)(row + 8) * DIM + col]) = make_float2(v2, v3);
            }
        }
    }
}

// ---------------------------------------------------------------------------
// Flash attention, fp16. Q-tile 128 (8 warps), K-tile 64.
// m16n8k16 mma; LDSM frags for Q/K/P; V via ldmatrix.trans from natural [k][d].
// K/V double-buffered with cp.async (overlap next tile load with compute).
// Q pre-scaled by QSCALE -> base-2 online softmax.
// ---------------------------------------------------------------------------
#define FROWB 144                               // 64 halves + 16B pad
#define QS_B  0
#define KS_B(s) (18432 + (s) * 9216)            // 128*144 .. two 64-row bufs
#define VS_B(s) (36864 + (s) * 9216)
#define PS_B  55296
#define FL_SMEMB (55296 + 128 * FROWB)          // 73728 B

__global__ __launch_bounds__(256, 2)
void flash_f16(const __half* __restrict__ Q,
               const __half* __restrict__ K,
               const __half* __restrict__ V,
               __half* __restrict__ O)
{
    extern __shared__ char smc[];
    const uint32_t smb = smem_u32(smc);

    const int tid  = threadIdx.x;
    const int lane = tid & 31;
    const int warp = tid >> 5;            // 0..7
    const int r    = lane >> 2;
    const int t    = lane & 3;
    const int qt   = (gridDim.x - 1) - blockIdx.x;   // heavy first
    const int h    = blockIdx.y;
    const int b    = blockIdx.z;
    const int q0   = qt * 128;
    const size_t base = (size_t)b * SEQ * DIM + (size_t)h * HDIM;

    const int arow  = ((lane >> 3) & 1) * 8 + (lane & 7);
    const int abyte = (lane >> 4) * 16;
    const int brow  = ((lane >> 4) & 1) * 8 + (lane & 7);
    const int bbyte = ((lane >> 3) & 1) * 16;
    const uint32_t qFrag = smb + QS_B + (warp * 16 + arow) * FROWB + abyte;
    const uint32_t pFrag = smb + PS_B + (warp * 16 + arow) * FROWB + abyte;

    // Q tile: 128 rows x 8 uint4 (4/thread)
    #pragma unroll
    for (int p = 0; p < 4; ++p) {
        int slot = tid + p * 256;
        int row  = slot >> 3;
        int c8   = (slot & 7) * 8;
        uint4 v = *reinterpret_cast<const uint4*>(
            &Q[base + (size_t)(q0 + row) * DIM + c8]);
        *reinterpret_cast<uint4*>(smc + QS_B + row * FROWB + c8 * 2) = v;
    }

    auto load_kv = [&](int kt, int s) {
        const __half* Kb = K + base + (size_t)(kt * 64) * DIM;
        const __half* Vb = V + base + (size_t)(kt * 64) * DIM;
        const uint32_t ks = smb + KS_B(s);
        const uint32_t vs = smb + VS_B(s);
        #pragma unroll
        for (int p = 0; p < 2; ++p) {            // 512 x 16B each
            int slot = tid + p * 256;
            int row  = slot >> 3;
            int c8   = (slot & 7) * 8;
            CP_ASYNC16(ks + row * FROWB + c8 * 2, Kb + (size_t)row * DIM + c8);
            CP_ASYNC16(vs + row * FROWB + c8 * 2, Vb + (size_t)row * DIM + c8);
        }
        CP_COMMIT();
    };

    float m_i[2] = {-CUDART_INF_F, -CUDART_INF_F};
    float l_i[2] = {0.0f, 0.0f};
    float o[8][4];
    #pragma unroll
    for (int ni = 0; ni < 8; ++ni)
        #pragma unroll
        for (int j = 0; j < 4; ++j) o[ni][j] = 0.0f;

    const int row_loc = warp * 16 + r;
    const int ktmax   = 2 * qt + 1;

    load_kv(0, 0);

    for (int kt = 0; kt <= ktmax; ++kt) {
        const int s  = kt & 1;
        const int k0 = kt * 64;

        CP_WAIT(0);
        __syncthreads();
        if (kt < ktmax) load_kv(kt + 1, s ^ 1);

        const uint32_t kFrag = smb + KS_B(s) + brow * FROWB + bbyte;
        const uint32_t vFrag = smb + VS_B(s) + arow * FROWB + abyte;

        const bool active = (k0 <= q0 + warp * 16 + 15);
        if (active) {
            // ---- S = Q K^T ----
            float sreg[8][4];
            #pragma unroll
            for (int ni = 0; ni < 8; ++ni)
                #pragma unroll
                for (int j = 0; j < 4; ++j) sreg[ni][j] = 0.0f;

            #pragma unroll
            for (int ks = 0; ks < 4; ++ks) {
                unsigned a0, a1, a2, a3;
                LDSM_X4(a0, a1, a2, a3, qFrag + ks * 32);
                #pragma unroll
                for (int pi = 0; pi < 4; ++pi) {
                    unsigned b0, b1, b2, b3;
                    LDSM_X4(b0, b1, b2, b3, kFrag + pi * (16 * FROWB) + ks * 32);
                    mma_f16(sreg[2*pi],   a0, a1, a2, a3, b0, b1);
                    mma_f16(sreg[2*pi+1], a0, a1, a2, a3, b2, b3);
                }
            }

            // ---- causal mask (diagonal tiles only) ----
            if (k0 + 63 > q0 + warp * 16) {
                const int rg0 = q0 + row_loc;
                #pragma unroll
                for (int ni = 0; ni < 8; ++ni) {
                    int cg = k0 + ni * 8 + 2 * t;
                    if (cg     > rg0    ) sreg[ni][0] = -CUDART_INF_F;
                    if (cg + 1 > rg0    ) sreg[ni][1] = -CUDART_INF_F;
                    if (cg     > rg0 + 8) sreg[ni][2] = -CUDART_INF_F;
                    if (cg + 1 > rg0 + 8) sreg[ni][3] = -CUDART_INF_F;
                }
            }

            // ---- base-2 online softmax ----
            #pragma unroll
            for (int hh = 0; hh < 2; ++hh) {
                float mx = -CUDART_INF_F;
                #pragma unroll
                for (int ni = 0; ni < 8; ++ni)
                    mx = fmaxf(mx, fmaxf(sreg[ni][hh * 2], sreg[ni][hh * 2 + 1]));
                mx = fmaxf(mx, __shfl_xor_sync(0xffffffffu, mx, 1, 4));
                mx = fmaxf(mx, __shfl_xor_sync(0xffffffffu, mx, 2, 4));
                float mnew  = fmaxf(m_i[hh], mx);
                float alpha = ex2f(m_i[hh] - mnew);
                m_i[hh] = mnew;
                float rs = 0.0f;
                #pragma unroll
                for (int ni = 0; ni < 8; ++ni) {
                    float p0 = ex2f(sreg[ni][hh * 2]     - mnew);
                    float p1 = ex2f(sreg[ni][hh * 2 + 1] - mnew);
                    sreg[ni][hh * 2]     = p0;
                    sreg[ni][hh * 2 + 1] = p1;
                    rs += p0 + p1;
                }
                rs += __shfl_xor_sync(0xffffffffu, rs, 1, 4);
                rs += __shfl_xor_sync(0xffffffffu, rs, 2, 4);
                l_i[hh] = l_i[hh] * alpha + rs;
                #pragma unroll
                for (int ni = 0; ni < 8; ++ni) {
                    o[ni][hh * 2]     *= alpha;
                    o[ni][hh * 2 + 1] *= alpha;
                }
            }

            // ---- stage P as fp16 (own rows; conflict-free 4B stores) ----
            #pragma unroll
            for (int ni = 0; ni < 8; ++ni) {
                *reinterpret_cast<__half2*>(
                    smc + PS_B + row_loc * FROWB + (ni * 8 + 2 * t) * 2) =
                    __floats2half2_rn(sreg[ni][0], sreg[ni][1]);
                *reinterpret_cast<__half2*>(
                    smc + PS_B + (row_loc + 8) * FROWB + (ni * 8 + 2 * t) * 2) =
                    __floats2half2_rn(sreg[ni][2], sreg[ni][3]);
            }
            __syncwarp();

            // ---- O += P V  (V B-frags via ldmatrix.trans from [k][d]) ----
            #pragma unroll
            for (int ks = 0; ks < 4; ++ks) {
                unsigned a0, a1, a2, a3;
                LDSM_X4(a0, a1, a2, a3, pFrag + ks * 32);
                #pragma unroll
                for (int pi = 0; pi < 4; ++pi) {
                    unsigned b0, b1, b2, b3;
                    LDSM_X4T(b0, b1, b2, b3,
                             vFrag + ks * (16 * FROWB) + pi * 32);
                    mma_f16(o[2*pi],   a0, a1, a2, a3, b0, b1);
                    mma_f16(o[2*pi+1], a0, a1, a2, a3, b2, b3);
                }
            }
        }
        __syncthreads();
    }

    // ---- normalize + fp16 store ----
    #pragma unroll
    for (int hh = 0; hh < 2; ++hh) {
        float inv_l = 1.0f / l_i[hh];
        int row = q0 + row_loc + hh * 8;
        #pragma unroll
        for (int ni = 0; ni < 8; ++ni) {
            *reinterpret_cast<__half2*>(
                &O[base + (size_t)row * DIM + ni * 8 + 2 * t]) =
                __floats2half2_rn(o[ni][hh * 2] * inv_l, o[ni][hh * 2 + 1] * inv_l);
        }
    }
}

// ---------------------------------------------------------------------------
// Launch
// ---------------------------------------------------------------------------
extern "C" void kernel_launch(void* const* d_in, const int* in_sizes, int n_in,
                              void* d_out, int out_size)
{
    const float* x  = (const float*)d_in[0];
    const float* Wq = (const float*)d_in[2];
    const float* Wk = (const float*)d_in[3];
    const float* Wv = (const float*)d_in[4];
    const float* Wo = (const float*)d_in[5];
    float* out = (float*)d_out;

    __half *QKV, *AOd, *Xh, *Wh;
    cudaGetSymbolAddress((void**)&QKV, g_QKV);
    cudaGetSymbolAddress((void**)&AOd, g_AO);
    cudaGetSymbolAddress((void**)&Xh,  g_Xh);
    cudaGetSymbolAddress((void**)&Wh,  g_Wh);

    static bool attr_set = false;
    if (!attr_set) {
        cudaFuncSetAttribute(flash_f16,
                             cudaFuncAttributeMaxDynamicSharedMemorySize, FL_SMEMB);
        cudaFuncSetAttribute((gemm_f16<true, true>),
                             cudaFuncAttributeMaxDynamicSharedMemorySize, SMEM_GEMM);
        cudaFuncSetAttribute((gemm_f16<false, false>),
                             cudaFuncAttributeMaxDynamicSharedMemorySize, SMEM_GEMM);
        attr_set = true;
    }

    cvt_x_k<<<1024, 256>>>((const float4*)x, (__half2*)Xh, MTOT * DIM / 4);
    cvt_w_k<<<dim3(128, 4), 256>>>((const float4*)Wq, (const float4*)Wk,
                                   (const float4*)Wv, (const float4*)Wo, (__half2*)Wh);

    // fused Q,K,V projections; Q pre-scaled by 0.125*log2(e)
    dim3 gQKV(DIM / 256, MTOT / 128, 3);   // (4, 64, 3)
    gemm_f16<true, true><<<gQKV, 512, SMEM_GEMM>>>(Xh, Wh, QKV);

    const __half* Qd = QKV;
    const __half* Kd = QKV + (size_t)MTOT * DIM;
    const __half* Vd = QKV + 2 * (size_t)MTOT * DIM;

    dim3 gF(SEQ / 128, NHEAD, BATCH);      // (16, 16, 4)
    flash_f16<<<gF, 256, FL_SMEMB>>>(Qd, Kd, Vd, AOd);

    dim3 gO(DIM / 256, MTOT / 128, 1);
    gemm_f16<false, false><<<gO, 512, SMEM_GEMM>>>(AOd, Wh + 3 * (size_t)DIM * DIM, out);
}

// round 8
// speedup vs baseline: 2.1077x; 1.0448x over previous
#include <cuda_runtime.h>
#include <cuda_fp16.h>
#include <math_constants.h>
#include <cstdint>

#define DIM    1024
#define NHEAD  16
#define HDIM   64
#define BATCH  4
#define SEQ    2048
#define MTOT   (BATCH * SEQ)      // 8192

// Q pre-scale: 64^-0.5 * log2(e)  (softmax done in base 2)
#define QSCALE 0.18033688011112042f

// ---------------------------------------------------------------------------
// Scratch (fp16 activations/weights)
// ---------------------------------------------------------------------------
__device__ __half g_QKV[3 * MTOT * DIM];   // Q(pre-scaled),K,V
__device__ __half g_AO [MTOT * DIM];       // attention out
__device__ __half g_Xh [MTOT * DIM];       // fp16 x
__device__ __half g_Wh [4 * DIM * DIM];    // fp16 Wq,Wk,Wv,Wo

// ---------------------------------------------------------------------------
// Helpers
// ---------------------------------------------------------------------------
__device__ __forceinline__ float ex2f(float x) {
    float y;
    asm("ex2.approx.f32 %0, %1;" : "=f"(y) : "f"(x));
    return y;
}

__device__ __forceinline__ uint32_t smem_u32(const void* p) {
    uint32_t a;
    asm("{ .reg .u64 t; cvta.to.shared.u64 t, %1; cvt.u32.u64 %0, t; }"
        : "=r"(a) : "l"(p));
    return a;
}

__device__ __forceinline__ unsigned pack_h2(float lo, float hi) {
    __half2 h = __floats2half2_rn(lo, hi);
    return *reinterpret_cast<unsigned*>(&h);
}

__device__ __forceinline__ void mma_f16(float* c,
                                        unsigned a0, unsigned a1,
                                        unsigned a2, unsigned a3,
                                        unsigned b0, unsigned b1) {
    asm volatile(
        "mma.sync.aligned.m16n8k16.row.col.f32.f16.f16.f32 "
        "{%0,%1,%2,%3},{%4,%5,%6,%7},{%8,%9},{%0,%1,%2,%3};\n"
        : "+f"(c[0]), "+f"(c[1]), "+f"(c[2]), "+f"(c[3])
        : "r"(a0), "r"(a1), "r"(a2), "r"(a3), "r"(b0), "r"(b1));
}

#define LDSM_X4(r0, r1, r2, r3, addr)                                         \
    asm volatile("ldmatrix.sync.aligned.m8n8.x4.shared.b16 {%0,%1,%2,%3}, [%4];" \
                 : "=r"(r0), "=r"(r1), "=r"(r2), "=r"(r3) : "r"(addr))

#define LDSM_X4T(r0, r1, r2, r3, addr)                                        \
    asm volatile("ldmatrix.sync.aligned.m8n8.x4.trans.shared.b16 {%0,%1,%2,%3}, [%4];" \
                 : "=r"(r0), "=r"(r1), "=r"(r2), "=r"(r3) : "r"(addr))

#define CP_ASYNC16(dst, src) \
    asm volatile("cp.async.cg.shared.global [%0], [%1], 16;" \
                 :: "r"(dst), "l"(src) : "memory")
#define CP_COMMIT() asm volatile("cp.async.commit_group;" ::: "memory")
#define CP_WAIT(N)  asm volatile("cp.async.wait_group %0;" :: "n"(N) : "memory")

// ---------------------------------------------------------------------------
// Pre-pass: fp32 -> fp16
// ---------------------------------------------------------------------------
__global__ void cvt_x_k(const float4* __restrict__ src,
                        __half2* __restrict__ dst, int n4)
{
    int i = blockIdx.x * blockDim.x + threadIdx.x;
    int stride = gridDim.x * blockDim.x;
    for (; i < n4; i += stride) {
        float4 v = src[i];
        dst[2 * i]     = __floats2half2_rn(v.x, v.y);
        dst[2 * i + 1] = __floats2half2_rn(v.z, v.w);
    }
}

__global__ void cvt_w_k(const float4* __restrict__ w0, const float4* __restrict__ w1,
                        const float4* __restrict__ w2, const float4* __restrict__ w3,
                        __half2* __restrict__ dst)
{
    const float4* src = (blockIdx.y == 0) ? w0 : (blockIdx.y == 1) ? w1
                       : (blockIdx.y == 2) ? w2 : w3;
    __half2* d = dst + (size_t)blockIdx.y * (DIM * DIM / 2);
    const int n4 = DIM * DIM / 4;
    int i = blockIdx.x * blockDim.x + threadIdx.x;
    int stride = gridDim.x * blockDim.x;
    for (; i < n4; i += stride) {
        float4 v = src[i];
        d[2 * i]     = __floats2half2_rn(v.x, v.y);
        d[2 * i + 1] = __floats2half2_rn(v.z, v.w);
    }
}

// ---------------------------------------------------------------------------
// FP16 GEMM: C = A * W^T. Tile 128(M) x 256(N), BK=64, 3-stage cp.async.
// 512 threads / 16 warps, warp tile 32x64, m16n8k16 mma, ldmatrix frags.
// ---------------------------------------------------------------------------
#define BK      64
#define NCH     (DIM / BK)              // 16
#define GROWB   144
#define A_STGB  (128 * GROWB)           // 18432
#define B_STGB  (256 * GROWB)           // 36864
#define STGB    (A_STGB + B_STGB)       // 55296
#define SMEM_GEMM (3 * STGB)            // 165888

template<bool HALF_OUT, bool SCALEQ>
__global__ __launch_bounds__(512, 1)
void gemm_f16(const __half* __restrict__ Abase,
              const __half* __restrict__ Wbase,
              void* __restrict__ Cvoid)
{
    extern __shared__ char smc[];
    const uint32_t sbase = smem_u32(smc);

    const int tid  = threadIdx.x;
    const int lane = tid & 31;
    const int warp = tid >> 5;           // 0..15
    const int wm   = warp & 3;
    const int wn   = warp >> 2;
    const int r    = lane >> 2;
    const int t    = lane & 3;
    const int m0   = blockIdx.y * 128;
    const int n0   = blockIdx.x * 256;

    const __half* A = Abase;
    const __half* W = Wbase + (size_t)blockIdx.z * DIM * DIM;

    float c[2][8][4];
    #pragma unroll
    for (int mi = 0; mi < 2; ++mi)
        #pragma unroll
        for (int ni = 0; ni < 8; ++ni)
            #pragma unroll
            for (int j = 0; j < 4; ++j) c[mi][ni][j] = 0.0f;

    const int arow  = ((lane >> 3) & 1) * 8 + (lane & 7);
    const int abyte = (lane >> 4) * 16;
    const int brow  = ((lane >> 4) & 1) * 8 + (lane & 7);
    const int bbyte = ((lane >> 3) & 1) * 16;
    const uint32_t aFrag = (uint32_t)((wm * 32 + arow) * GROWB + abyte);
    const uint32_t bFrag = (uint32_t)(A_STGB + (wn * 64 + brow) * GROWB + bbyte);

    auto load_stage = [&](int ch, int s) {
        const __half* Ab = A + (size_t)m0 * DIM + ch * BK;
        const __half* Wb = W + (size_t)n0 * DIM + ch * BK;
        const uint32_t as = sbase + s * STGB;
        const uint32_t bs = as + A_STGB;
        #pragma unroll
        for (int p = 0; p < 2; ++p) {
            int slot = tid + p * 512;
            int row  = slot >> 3;
            int c8   = (slot & 7) * 8;
            CP_ASYNC16(as + row * GROWB + c8 * 2,
                       Ab + (size_t)row * DIM + c8);
        }
        #pragma unroll
        for (int p = 0; p < 4; ++p) {
            int slot = tid + p * 512;
            int row  = slot >> 3;
            int c8   = (slot & 7) * 8;
            CP_ASYNC16(bs + row * GROWB + c8 * 2,
                       Wb + (size_t)row * DIM + c8);
        }
        CP_COMMIT();
    };

    load_stage(0, 0);
    load_stage(1, 1);

    for (int ch = 0; ch < NCH; ++ch) {
        if (ch < NCH - 1) { CP_WAIT(1); } else { CP_WAIT(0); }
        __syncthreads();
        if (ch + 2 < NCH) load_stage(ch + 2, (ch + 2) % 3);

        const uint32_t stg = sbase + (ch % 3) * STGB;
        const uint32_t aB  = stg + aFrag;
        const uint32_t bB  = stg + bFrag;

        #pragma unroll
        for (int ks = 0; ks < 4; ++ks) {
            unsigned a[2][4], b[4][4];
            #pragma unroll
            for (int mi = 0; mi < 2; ++mi)
                LDSM_X4(a[mi][0], a[mi][1], a[mi][2], a[mi][3],
                        aB + mi * (16 * GROWB) + ks * 32);
            #pragma unroll
            for (int pi = 0; pi < 4; ++pi)
                LDSM_X4(b[pi][0], b[pi][1], b[pi][2], b[pi][3],
                        bB + pi * (16 * GROWB) + ks * 32);
            #pragma unroll
            for (int mi = 0; mi < 2; ++mi)
                #pragma unroll
                for (int pi = 0; pi < 4; ++pi) {
                    mma_f16(c[mi][2*pi],   a[mi][0], a[mi][1], a[mi][2], a[mi][3],
                            b[pi][0], b[pi][1]);
                    mma_f16(c[mi][2*pi+1], a[mi][0], a[mi][1], a[mi][2], a[mi][3],
                            b[pi][2], b[pi][3]);
                }
        }
    }

    const float sc = (SCALEQ && blockIdx.z == 0) ? QSCALE : 1.0f;
    #pragma unroll
    for (int mi = 0; mi < 2; ++mi) {
        #pragma unroll
        for (int ni = 0; ni < 8; ++ni) {
            int row = m0 + wm * 32 + mi * 16 + r;
            int col = n0 + wn * 64 + ni * 8 + 2 * t;
            float v0 = c[mi][ni][0] * sc, v1 = c[mi][ni][1] * sc;
            float v2 = c[mi][ni][2] * sc, v3 = c[mi][ni][3] * sc;
            if (HALF_OUT) {
                __half* C = (__half*)Cvoid + (size_t)blockIdx.z * MTOT * DIM;
                *reinterpret_cast<__half2*>(&C[(size_t)row * DIM + col]) =
                    __floats2half2_rn(v0, v1);
                *reinterpret_cast<__half2*>(&C[(size_t)(row + 8) * DIM + col]) =
                    __floats2half2_rn(v2, v3);
            } else {
                float* C = (float*)Cvoid;
                *reinterpret_cast<float2*>(&C[(size_t)row * DIM + col])       = make_float2(v0, v1);
                *reinterpret_cast<float2*>(&C[(size_t)(row + 8) * DIM + col]) = make_float2(v2, v3);
            }
        }
    }
}

// ---------------------------------------------------------------------------
// Flash attention, fp16, register-resident P (no smem round-trip).
// Q-tile 128 (8 warps), K-tile 64, K/V double-buffered cp.async.
// Q fragments hoisted to registers once per block.
// ---------------------------------------------------------------------------
#define FROWB 144                               // 64 halves + 16B pad
#define QS_B  0
#define KS_B(s) (18432 + (s) * 9216)
#define VS_B(s) (36864 + (s) * 9216)
#define FL_SMEMB 55296

__global__ __launch_bounds__(256, 2)
void flash_f16(const __half* __restrict__ Q,
               const __half* __restrict__ K,
               const __half* __restrict__ V,
               __half* __restrict__ O)
{
    extern __shared__ char smc[];
    const uint32_t smb = smem_u32(smc);

    const int tid  = threadIdx.x;
    const int lane = tid & 31;
    const int warp = tid >> 5;            // 0..7
    const int r    = lane >> 2;
    const int t    = lane & 3;
    const int qt   = (gridDim.x - 1) - blockIdx.x;   // heavy first
    const int h    = blockIdx.y;
    const int b    = blockIdx.z;
    const int q0   = qt * 128;
    const size_t base = (size_t)b * SEQ * DIM + (size_t)h * HDIM;

    const int arow  = ((lane >> 3) & 1) * 8 + (lane & 7);
    const int abyte = (lane >> 4) * 16;
    const int brow  = ((lane >> 4) & 1) * 8 + (lane & 7);
    const int bbyte = ((lane >> 3) & 1) * 16;
    const uint32_t qFrag = smb + QS_B + (warp * 16 + arow) * FROWB + abyte;

    auto load_kv = [&](int kt, int s) {
        const __half* Kb = K + base + (size_t)(kt * 64) * DIM;
        const __half* Vb = V + base + (size_t)(kt * 64) * DIM;
        const uint32_t ks = smb + KS_B(s);
        const uint32_t vs = smb + VS_B(s);
        #pragma unroll
        for (int p = 0; p < 2; ++p) {
            int slot = tid + p * 256;
            int row  = slot >> 3;
            int c8   = (slot & 7) * 8;
            CP_ASYNC16(ks + row * FROWB + c8 * 2, Kb + (size_t)row * DIM + c8);
            CP_ASYNC16(vs + row * FROWB + c8 * 2, Vb + (size_t)row * DIM + c8);
        }
        CP_COMMIT();
    };

    // kick off first K/V tile load, then stage Q
    load_kv(0, 0);

    #pragma unroll
    for (int p = 0; p < 4; ++p) {
        int slot = tid + p * 256;
        int row  = slot >> 3;
        int c8   = (slot & 7) * 8;
        uint4 v = *reinterpret_cast<const uint4*>(
            &Q[base + (size_t)(q0 + row) * DIM + c8]);
        *reinterpret_cast<uint4*>(smc + QS_B + row * FROWB + c8 * 2) = v;
    }
    __syncthreads();

    // hoist Q fragments into registers (constant across the whole kt loop)
    unsigned qa[4][4];
    #pragma unroll
    for (int ks = 0; ks < 4; ++ks)
        LDSM_X4(qa[ks][0], qa[ks][1], qa[ks][2], qa[ks][3], qFrag + ks * 32);

    float m_i[2] = {-CUDART_INF_F, -CUDART_INF_F};
    float l_i[2] = {0.0f, 0.0f};
    float o[8][4];
    #pragma unroll
    for (int ni = 0; ni < 8; ++ni)
        #pragma unroll
        for (int j = 0; j < 4; ++j) o[ni][j] = 0.0f;

    const int row_loc = warp * 16 + r;
    const int ktmax   = 2 * qt + 1;

    for (int kt = 0; kt <= ktmax; ++kt) {
        const int s  = kt & 1;
        const int k0 = kt * 64;

        CP_WAIT(0);
        __syncthreads();
        if (kt < ktmax) load_kv(kt + 1, s ^ 1);

        const uint32_t kFrag = smb + KS_B(s) + brow * FROWB + bbyte;
        const uint32_t vFrag = smb + VS_B(s) + arow * FROWB + abyte;

        const bool active = (k0 <= q0 + warp * 16 + 15);
        if (active) {
            // ---- S = Q K^T ----
            float sreg[8][4];
            #pragma unroll
            for (int ni = 0; ni < 8; ++ni)
                #pragma unroll
                for (int j = 0; j < 4; ++j) sreg[ni][j] = 0.0f;

            #pragma unroll
            for (int ks = 0; ks < 4; ++ks) {
                #pragma unroll
                for (int pi = 0; pi < 4; ++pi) {
                    unsigned b0, b1, b2, b3;
                    LDSM_X4(b0, b1, b2, b3, kFrag + pi * (16 * FROWB) + ks * 32);
                    mma_f16(sreg[2*pi],   qa[ks][0], qa[ks][1], qa[ks][2], qa[ks][3], b0, b1);
                    mma_f16(sreg[2*pi+1], qa[ks][0], qa[ks][1], qa[ks][2], qa[ks][3], b2, b3);
                }
            }

            // ---- causal mask (diagonal tiles only) ----
            if (k0 + 63 > q0 + warp * 16) {
                const int rg0 = q0 + row_loc;
                #pragma unroll
                for (int ni = 0; ni < 8; ++ni) {
                    int cg = k0 + ni * 8 + 2 * t;
                    if (cg     > rg0    ) sreg[ni][0] = -CUDART_INF_F;
                    if (cg + 1 > rg0    ) sreg[ni][1] = -CUDART_INF_F;
                    if (cg     > rg0 + 8) sreg[ni][2] = -CUDART_INF_F;
                    if (cg + 1 > rg0 + 8) sreg[ni][3] = -CUDART_INF_F;
                }
            }

            // ---- base-2 online softmax ----
            #pragma unroll
            for (int hh = 0; hh < 2; ++hh) {
                float mx = -CUDART_INF_F;
                #pragma unroll
                for (int ni = 0; ni < 8; ++ni)
                    mx = fmaxf(mx, fmaxf(sreg[ni][hh * 2], sreg[ni][hh * 2 + 1]));
                mx = fmaxf(mx, __shfl_xor_sync(0xffffffffu, mx, 1, 4));
                mx = fmaxf(mx, __shfl_xor_sync(0xffffffffu, mx, 2, 4));
                float mnew  = fmaxf(m_i[hh], mx);
                float alpha = ex2f(m_i[hh] - mnew);
                m_i[hh] = mnew;
                float rs = 0.0f;
                #pragma unroll
                for (int ni = 0; ni < 8; ++ni) {
                    float p0 = ex2f(sreg[ni][hh * 2]     - mnew);
                    float p1 = ex2f(sreg[ni][hh * 2 + 1] - mnew);
                    sreg[ni][hh * 2]     = p0;
                    sreg[ni][hh * 2 + 1] = p1;
                    rs += p0 + p1;
                }
                rs += __shfl_xor_sync(0xffffffffu, rs, 1, 4);
                rs += __shfl_xor_sync(0xffffffffu, rs, 2, 4);
                l_i[hh] = l_i[hh] * alpha + rs;
                #pragma unroll
                for (int ni = 0; ni < 8; ++ni) {
                    o[ni][hh * 2]     *= alpha;
                    o[ni][hh * 2 + 1] *= alpha;
                }
            }

            // ---- C-frag -> A-frag register conversion (no smem!) ----
            // A-frag for k-block ks: a0 = S[2ks](c0,c1), a1 = S[2ks](c2,c3),
            //                        a2 = S[2ks+1](c0,c1), a3 = S[2ks+1](c2,c3)
            unsigned pa[4][4];
            #pragma unroll
            for (int ks = 0; ks < 4; ++ks) {
                pa[ks][0] = pack_h2(sreg[2*ks][0],   sreg[2*ks][1]);
                pa[ks][1] = pack_h2(sreg[2*ks][2],   sreg[2*ks][3]);
                pa[ks][2] = pack_h2(sreg[2*ks+1][0], sreg[2*ks+1][1]);
                pa[ks][3] = pack_h2(sreg[2*ks+1][2], sreg[2*ks+1][3]);
            }

            // ---- O += P V  (V B-frags via ldmatrix.trans from [k][d]) ----
            #pragma unroll
            for (int ks = 0; ks < 4; ++ks) {
                #pragma unroll
                for (int pi = 0; pi < 4; ++pi) {
                    unsigned b0, b1, b2, b3;
                    LDSM_X4T(b0, b1, b2, b3,
                             vFrag + ks * (16 * FROWB) + pi * 32);
                    mma_f16(o[2*pi],   pa[ks][0], pa[ks][1], pa[ks][2], pa[ks][3], b0, b1);
                    mma_f16(o[2*pi+1], pa[ks][0], pa[ks][1], pa[ks][2], pa[ks][3], b2, b3);
                }
            }
        }
        __syncthreads();
    }

    // ---- normalize + fp16 store ----
    #pragma unroll
    for (int hh = 0; hh < 2; ++hh) {
        float inv_l = 1.0f / l_i[hh];
        int row = q0 + row_loc + hh * 8;
        #pragma unroll
        for (int ni = 0; ni < 8; ++ni) {
            *reinterpret_cast<__half2*>(
                &O[base + (size_t)row * DIM + ni * 8 + 2 * t]) =
                __floats2half2_rn(o[ni][hh * 2] * inv_l, o[ni][hh * 2 + 1] * inv_l);
        }
    }
}

// ---------------------------------------------------------------------------
// Launch
// ---------------------------------------------------------------------------
extern "C" void kernel_launch(void* const* d_in, const int* in_sizes, int n_in,
                              void* d_out, int out_size)
{
    const float* x  = (const float*)d_in[0];
    const float* Wq = (const float*)d_in[2];
    const float* Wk = (const float*)d_in[3];
    const float* Wv = (const float*)d_in[4];
    const float* Wo = (const float*)d_in[5];
    float* out = (float*)d_out;

    __half *QKV, *AOd, *Xh, *Wh;
    cudaGetSymbolAddress((void**)&QKV, g_QKV);
    cudaGetSymbolAddress((void**)&AOd, g_AO);
    cudaGetSymbolAddress((void**)&Xh,  g_Xh);
    cudaGetSymbolAddress((void**)&Wh,  g_Wh);

    static bool attr_set = false;
    if (!attr_set) {
        cudaFuncSetAttribute(flash_f16,
                             cudaFuncAttributeMaxDynamicSharedMemorySize, FL_SMEMB);
        cudaFuncSetAttribute((gemm_f16<true, true>),
                             cudaFuncAttributeMaxDynamicSharedMemorySize, SMEM_GEMM);
        cudaFuncSetAttribute((gemm_f16<false, false>),
                             cudaFuncAttributeMaxDynamicSharedMemorySize, SMEM_GEMM);
        attr_set = true;
    }

    cvt_x_k<<<1024, 256>>>((const float4*)x, (__half2*)Xh, MTOT * DIM / 4);
    cvt_w_k<<<dim3(128, 4), 256>>>((const float4*)Wq, (const float4*)Wk,
                                   (const float4*)Wv, (const float4*)Wo, (__half2*)Wh);

    // fused Q,K,V projections; Q pre-scaled by 0.125*log2(e)
    dim3 gQKV(DIM / 256, MTOT / 128, 3);   // (4, 64, 3)
    gemm_f16<true, true><<<gQKV, 512, SMEM_GEMM>>>(Xh, Wh, QKV);

    const __half* Qd = QKV;
    const __half* Kd = QKV + (size_t)MTOT * DIM;
    const __half* Vd = QKV + 2 * (size_t)MTOT * DIM;

    dim3 gF(SEQ / 128, NHEAD, BATCH);      // (16, 16, 4)
    flash_f16<<<gF, 256, FL_SMEMB>>>(Qd, Kd, Vd, AOd);

    dim3 gO(DIM / 256, MTOT / 128, 1);
    gemm_f16<false, false><<<gO, 512, SMEM_GEMM>>>(AOd, Wh + 3 * (size_t)DIM * DIM, out);
}